// round 1
// baseline (speedup 1.0000x reference)
#include <cuda_runtime.h>
#include <math.h>

#define CH     512
#define NPIX   4096
#define BATCH  4
#define GROUPS 32
#define CPG    16      // channels per group

// ---------------- scratch (device globals: allocation-guard safe) ----------
__device__ float g_hn[(size_t)BATCH * CH * NPIX];     // 32 MB
__device__ float g_q [(size_t)BATCH * CH * NPIX];
__device__ float g_k [(size_t)BATCH * CH * NPIX];
__device__ float g_v [(size_t)BATCH * CH * NPIX];
__device__ float g_o [(size_t)BATCH * CH * NPIX];
__device__ float g_S [(size_t)BATCH * NPIX * NPIX];   // 256 MB
__device__ float g_mean[BATCH * GROUPS];
__device__ float g_rstd[BATCH * GROUPS];

// ---------------- GroupNorm ------------------------------------------------
__global__ void gn_stats(const float* __restrict__ x) {
    int bg = blockIdx.x;  // b*32 + g ; group channels are contiguous
    const float4* p = (const float4*)(x + (long long)bg * CPG * NPIX);
    float s = 0.f, sq = 0.f;
    for (int i = threadIdx.x; i < CPG * NPIX / 4; i += blockDim.x) {
        float4 v = p[i];
        s  += v.x + v.y + v.z + v.w;
        sq += v.x*v.x + v.y*v.y + v.z*v.z + v.w*v.w;
    }
    __shared__ float sh_s[8], sh_q[8];
    #pragma unroll
    for (int o = 16; o; o >>= 1) {
        s  += __shfl_xor_sync(0xffffffffu, s,  o);
        sq += __shfl_xor_sync(0xffffffffu, sq, o);
    }
    if ((threadIdx.x & 31) == 0) { sh_s[threadIdx.x >> 5] = s; sh_q[threadIdx.x >> 5] = sq; }
    __syncthreads();
    if (threadIdx.x == 0) {
        float ts = 0.f, tq = 0.f;
        #pragma unroll
        for (int i = 0; i < 8; i++) { ts += sh_s[i]; tq += sh_q[i]; }
        const float inv = 1.f / (float)(CPG * NPIX);
        float m   = ts * inv;
        float var = tq * inv - m * m;
        g_mean[bg] = m;
        g_rstd[bg] = rsqrtf(var + 1e-6f);
    }
}

__global__ void gn_apply(const float* __restrict__ x,
                         const float* __restrict__ gamma,
                         const float* __restrict__ beta) {
    long long i = (long long)blockIdx.x * blockDim.x + threadIdx.x;  // float4 index
    long long e = i * 4;                    // element index in [b][c][n]
    int c  = (int)((e >> 12) & (CH - 1));   // /4096 % 512
    int bg = (int)(e >> 16);                // /(16*4096) = b*32 + g
    float r  = g_rstd[bg], m = g_mean[bg];
    float ga = gamma[c] * r;
    float be = beta[c] - m * ga;
    float4 v = ((const float4*)x)[i];
    float4 o;
    o.x = v.x * ga + be; o.y = v.y * ga + be;
    o.z = v.z * ga + be; o.w = v.w * ga + be;
    ((float4*)g_hn)[i] = o;
}

// ---------------- generic 128x128x8 SGEMM ---------------------------------
// C[i*N+j] = alpha * sum_k Aop(i,k)*Bop(j,k) (+ bias[i]) (+ resid[i*N+j])
// A_KC: A[i*K+k] (k contiguous) else A[k*M+i]
// B_KC: B[j*K+k] (k contiguous) else B[k*N+j]
template<bool A_KC, bool B_KC>
__global__ void __launch_bounds__(256)
gemm128(const float* __restrict__ Ag, const float* __restrict__ Bg,
        float* __restrict__ Cg,
        int M, int N, int K,
        long long sA, long long sB, long long sC,
        float alpha, const float* __restrict__ bias,
        const float* __restrict__ resid, long long sR)
{
    __shared__ float As[8][128];
    __shared__ float Bs[8][128];
    const float* A = Ag + (long long)blockIdx.z * sA;
    const float* B = Bg + (long long)blockIdx.z * sB;
    float*       C = Cg + (long long)blockIdx.z * sC;
    const int bi = blockIdx.y * 128, bj = blockIdx.x * 128;
    const int t = threadIdx.x, tx = t & 15, ty = t >> 4;

    float acc[8][8];
    #pragma unroll
    for (int a = 0; a < 8; a++)
        #pragma unroll
        for (int b2 = 0; b2 < 8; b2++) acc[a][b2] = 0.f;

    for (int k0 = 0; k0 < K; k0 += 8) {
        if (A_KC) {
            int row = t >> 1, kk = (t & 1) << 2;
            float4 v = *(const float4*)(A + (long long)(bi + row) * K + k0 + kk);
            As[kk + 0][row] = v.x; As[kk + 1][row] = v.y;
            As[kk + 2][row] = v.z; As[kk + 3][row] = v.w;
        } else {
            int kk = t >> 5, i4 = (t & 31) << 2;
            *(float4*)&As[kk][i4] = *(const float4*)(A + (long long)(k0 + kk) * M + bi + i4);
        }
        if (B_KC) {
            int row = t >> 1, kk = (t & 1) << 2;
            float4 v = *(const float4*)(B + (long long)(bj + row) * K + k0 + kk);
            Bs[kk + 0][row] = v.x; Bs[kk + 1][row] = v.y;
            Bs[kk + 2][row] = v.z; Bs[kk + 3][row] = v.w;
        } else {
            int kk = t >> 5, j4 = (t & 31) << 2;
            *(float4*)&Bs[kk][j4] = *(const float4*)(B + (long long)(k0 + kk) * N + bj + j4);
        }
        __syncthreads();
        #pragma unroll
        for (int kk = 0; kk < 8; kk++) {
            float a[8], bb[8];
            *(float4*)&a[0]  = *(const float4*)&As[kk][ty << 2];
            *(float4*)&a[4]  = *(const float4*)&As[kk][64 + (ty << 2)];
            *(float4*)&bb[0] = *(const float4*)&Bs[kk][tx << 2];
            *(float4*)&bb[4] = *(const float4*)&Bs[kk][64 + (tx << 2)];
            #pragma unroll
            for (int ii = 0; ii < 8; ii++)
                #pragma unroll
                for (int jj = 0; jj < 8; jj++)
                    acc[ii][jj] = fmaf(a[ii], bb[jj], acc[ii][jj]);
        }
        __syncthreads();
    }

    #pragma unroll
    for (int ii = 0; ii < 8; ii++) {
        int i = bi + (ty << 2) + (ii & 3) + ((ii & 4) ? 64 : 0);
        float bv = bias ? bias[i] : 0.f;
        #pragma unroll
        for (int half = 0; half < 2; half++) {
            int j = bj + (tx << 2) + half * 64;
            float4 o;
            o.x = acc[ii][half * 4 + 0] * alpha + bv;
            o.y = acc[ii][half * 4 + 1] * alpha + bv;
            o.z = acc[ii][half * 4 + 2] * alpha + bv;
            o.w = acc[ii][half * 4 + 3] * alpha + bv;
            if (resid) {
                float4 r = *(const float4*)(resid + (long long)blockIdx.z * sR +
                                            (long long)i * N + j);
                o.x += r.x; o.y += r.y; o.z += r.z; o.w += r.w;
            }
            *(float4*)(C + (long long)i * N + j) = o;
        }
    }
}

// ---------------- row softmax (4096 per row) -------------------------------
__global__ void softmax_rows(float* __restrict__ S) {
    float* p = S + (long long)blockIdx.x * NPIX;
    const int t = threadIdx.x;
    float4 v[4];
    float mx = -1e30f;
    #pragma unroll
    for (int j = 0; j < 4; j++) {
        v[j] = ((const float4*)p)[t + j * 256];
        mx = fmaxf(mx, fmaxf(fmaxf(v[j].x, v[j].y), fmaxf(v[j].z, v[j].w)));
    }
    __shared__ float shm[8], shs[8];
    #pragma unroll
    for (int o = 16; o; o >>= 1) mx = fmaxf(mx, __shfl_xor_sync(0xffffffffu, mx, o));
    if ((t & 31) == 0) shm[t >> 5] = mx;
    __syncthreads();
    mx = shm[0];
    #pragma unroll
    for (int i = 1; i < 8; i++) mx = fmaxf(mx, shm[i]);

    float s = 0.f;
    #pragma unroll
    for (int j = 0; j < 4; j++) {
        v[j].x = __expf(v[j].x - mx); v[j].y = __expf(v[j].y - mx);
        v[j].z = __expf(v[j].z - mx); v[j].w = __expf(v[j].w - mx);
        s += v[j].x + v[j].y + v[j].z + v[j].w;
    }
    #pragma unroll
    for (int o = 16; o; o >>= 1) s += __shfl_xor_sync(0xffffffffu, s, o);
    if ((t & 31) == 0) shs[t >> 5] = s;
    __syncthreads();
    s = 0.f;
    #pragma unroll
    for (int i = 0; i < 8; i++) s += shs[i];
    float inv = 1.f / s;
    #pragma unroll
    for (int j = 0; j < 4; j++) {
        v[j].x *= inv; v[j].y *= inv; v[j].z *= inv; v[j].w *= inv;
        ((float4*)p)[t + j * 256] = v[j];
    }
}

// ---------------- launch ---------------------------------------------------
extern "C" void kernel_launch(void* const* d_in, const int* in_sizes, int n_in,
                              void* d_out, int out_size) {
    const float* x     = (const float*)d_in[0];
    const float* gamma = (const float*)d_in[1];
    const float* beta  = (const float*)d_in[2];
    const float* wq    = (const float*)d_in[3];
    const float* bq    = (const float*)d_in[4];
    const float* wk    = (const float*)d_in[5];
    const float* bk    = (const float*)d_in[6];
    const float* wv    = (const float*)d_in[7];
    const float* bv    = (const float*)d_in[8];
    const float* wo    = (const float*)d_in[9];
    const float* bo    = (const float*)d_in[10];
    float* out = (float*)d_out;

    float *hn, *q, *k, *v, *o, *S;
    cudaGetSymbolAddress((void**)&hn, g_hn);
    cudaGetSymbolAddress((void**)&q,  g_q);
    cudaGetSymbolAddress((void**)&k,  g_k);
    cudaGetSymbolAddress((void**)&v,  g_v);
    cudaGetSymbolAddress((void**)&o,  g_o);
    cudaGetSymbolAddress((void**)&S,  g_S);

    const long long P  = (long long)CH * NPIX;     // 2097152
    const long long PS = (long long)NPIX * NPIX;   // 16777216
    const float scale  = 0.044194173824159216f;    // 512^-0.5

    gn_stats<<<BATCH * GROUPS, 256>>>(x);
    gn_apply<<<(int)((long long)BATCH * CH * NPIX / 4 / 256), 256>>>(x, gamma, beta);

    dim3 gProj(NPIX / 128, CH / 128, BATCH);   // (32, 4, 4)
    gemm128<true,  false><<<gProj, 256>>>(wq, hn, q, CH, NPIX, CH, 0, P, P, 1.f, bq, nullptr, 0);
    gemm128<true,  false><<<gProj, 256>>>(wk, hn, k, CH, NPIX, CH, 0, P, P, 1.f, bk, nullptr, 0);
    gemm128<true,  false><<<gProj, 256>>>(wv, hn, v, CH, NPIX, CH, 0, P, P, 1.f, bv, nullptr, 0);

    dim3 gS(NPIX / 128, NPIX / 128, BATCH);    // (32, 32, 4)
    gemm128<false, false><<<gS, 256>>>(q, k, S, NPIX, NPIX, CH, P, P, PS, scale, nullptr, nullptr, 0);

    softmax_rows<<<BATCH * NPIX, 256>>>(S);

    gemm128<true,  true ><<<gProj, 256>>>(v, S, o, CH, NPIX, NPIX, P, PS, P, 1.f, nullptr, nullptr, 0);
    gemm128<true,  false><<<gProj, 256>>>(wo, o, out, CH, NPIX, CH, 0, P, P, 1.f, bo, x, P);
}

// round 2
// speedup vs baseline: 2.3234x; 2.3234x over previous
#include <cuda_runtime.h>
#include <math.h>
#include <stdint.h>

#define CH     512
#define NPIX   4096
#define BATCH  4
#define GROUPS 32
#define CPG    16      // channels per group

// ---------------- scratch (device globals: allocation-guard safe) ----------
__device__ float g_hn[(size_t)BATCH * CH * NPIX];     // 32 MB
__device__ float g_q [(size_t)BATCH * CH * NPIX];
__device__ float g_k [(size_t)BATCH * CH * NPIX];
__device__ float g_v [(size_t)BATCH * CH * NPIX];
__device__ float g_o [(size_t)BATCH * CH * NPIX];
__device__ float g_S [(size_t)BATCH * NPIX * NPIX];   // 256 MB
__device__ float g_mean[BATCH * GROUPS];
__device__ float g_rstd[BATCH * GROUPS];

// ---------------- GroupNorm ------------------------------------------------
__global__ void gn_stats(const float* __restrict__ x) {
    int bg = blockIdx.x;
    const float4* p = (const float4*)(x + (long long)bg * CPG * NPIX);
    float s = 0.f, sq = 0.f;
    for (int i = threadIdx.x; i < CPG * NPIX / 4; i += blockDim.x) {
        float4 v = p[i];
        s  += v.x + v.y + v.z + v.w;
        sq += v.x*v.x + v.y*v.y + v.z*v.z + v.w*v.w;
    }
    __shared__ float sh_s[8], sh_q[8];
    #pragma unroll
    for (int o = 16; o; o >>= 1) {
        s  += __shfl_xor_sync(0xffffffffu, s,  o);
        sq += __shfl_xor_sync(0xffffffffu, sq, o);
    }
    if ((threadIdx.x & 31) == 0) { sh_s[threadIdx.x >> 5] = s; sh_q[threadIdx.x >> 5] = sq; }
    __syncthreads();
    if (threadIdx.x == 0) {
        float ts = 0.f, tq = 0.f;
        #pragma unroll
        for (int i = 0; i < 8; i++) { ts += sh_s[i]; tq += sh_q[i]; }
        const float inv = 1.f / (float)(CPG * NPIX);
        float m   = ts * inv;
        float var = tq * inv - m * m;
        g_mean[bg] = m;
        g_rstd[bg] = rsqrtf(var + 1e-6f);
    }
}

__global__ void gn_apply(const float* __restrict__ x,
                         const float* __restrict__ gamma,
                         const float* __restrict__ beta) {
    long long i = (long long)blockIdx.x * blockDim.x + threadIdx.x;
    long long e = i * 4;
    int c  = (int)((e >> 12) & (CH - 1));
    int bg = (int)(e >> 16);
    float r  = g_rstd[bg], m = g_mean[bg];
    float ga = gamma[c] * r;
    float be = beta[c] - m * ga;
    float4 v = ((const float4*)x)[i];
    float4 o;
    o.x = v.x * ga + be; o.y = v.y * ga + be;
    o.z = v.z * ga + be; o.w = v.w * ga + be;
    ((float4*)g_hn)[i] = o;
}

// ---------------- tf32 tensor-core GEMM ------------------------------------
// C[i*N+j] = alpha * sum_k Aop(i,k)*Bop(j,k) (+ bias[i]) (+ resid)
// A_KC: Aop(i,k) = A[i*lda + k]  else A[k*lda + i]
// B_KC: Bop(j,k) = B[j*ldb + k]  else B[k*ldb + j]

__device__ __forceinline__ uint32_t f2tf(float x) {
    uint32_t r;
    asm("cvt.rna.tf32.f32 %0, %1;" : "=r"(r) : "f"(x));
    return r;
}

__device__ __forceinline__ void mma_tf32(float* d, const uint32_t* a, const uint32_t* b) {
    asm volatile(
        "mma.sync.aligned.m16n8k8.row.col.f32.tf32.tf32.f32 "
        "{%0,%1,%2,%3}, {%4,%5,%6,%7}, {%8,%9}, {%0,%1,%2,%3};\n"
        : "+f"(d[0]), "+f"(d[1]), "+f"(d[2]), "+f"(d[3])
        : "r"(a[0]), "r"(a[1]), "r"(a[2]), "r"(a[3]), "r"(b[0]), "r"(b[1]));
}

#define ROWP 136   // smem row pitch in floats (16 k-rows x 136)

template<bool KC>
__device__ __forceinline__ void load_tile(const float* __restrict__ G, int ld,
                                          int base, int k0, float4* r) {
    const int t = threadIdx.x;
    if (KC) {
        #pragma unroll
        for (int u = 0; u < 2; u++) {
            int idx = t + u * 256;
            int row = idx >> 2, kq = idx & 3;
            r[u] = *(const float4*)(G + (long long)(base + row) * ld + k0 + 4 * kq);
        }
    } else {
        #pragma unroll
        for (int u = 0; u < 2; u++) {
            int idx = t + u * 256;
            int kk = idx >> 5, m4 = idx & 31;
            r[u] = *(const float4*)(G + (long long)(k0 + kk) * ld + base + 4 * m4);
        }
    }
}

template<bool KC>
__device__ __forceinline__ void store_tile(float* S, const float4* r) {
    const int t = threadIdx.x;
    if (KC) {
        #pragma unroll
        for (int u = 0; u < 2; u++) {
            int idx = t + u * 256;
            int row = idx >> 2, kq = idx & 3;
            S[(4*kq + 0) * ROWP + row] = __uint_as_float(f2tf(r[u].x));
            S[(4*kq + 1) * ROWP + row] = __uint_as_float(f2tf(r[u].y));
            S[(4*kq + 2) * ROWP + row] = __uint_as_float(f2tf(r[u].z));
            S[(4*kq + 3) * ROWP + row] = __uint_as_float(f2tf(r[u].w));
        }
    } else {
        #pragma unroll
        for (int u = 0; u < 2; u++) {
            int idx = t + u * 256;
            int kk = idx >> 5, m4 = idx & 31;
            float4 v;
            v.x = __uint_as_float(f2tf(r[u].x));
            v.y = __uint_as_float(f2tf(r[u].y));
            v.z = __uint_as_float(f2tf(r[u].z));
            v.w = __uint_as_float(f2tf(r[u].w));
            *(float4*)&S[kk * ROWP + 4 * m4] = v;
        }
    }
}

template<bool A_KC, bool B_KC>
__global__ void __launch_bounds__(256)
gemm_tc(const float* __restrict__ Ag, const float* __restrict__ Bg,
        float* __restrict__ Cg,
        int M, int N, int K, int lda, int ldb,
        long long sA, long long sB, long long sC,
        float alpha, const float* __restrict__ bias,
        const float* __restrict__ resid, long long sR)
{
    __shared__ float As[2][16 * ROWP];
    __shared__ float Bs[2][16 * ROWP];

    const float* A = Ag + (long long)blockIdx.z * sA;
    const float* B = Bg + (long long)blockIdx.z * sB;
    float*       C = Cg + (long long)blockIdx.z * sC;
    const int bi = blockIdx.y * 128, bj = blockIdx.x * 128;

    const int t    = threadIdx.x;
    const int lane = t & 31, warp = t >> 5;
    const int wm = warp >> 2, wn = warp & 3;     // 2 x 4 warp grid
    const int r  = lane >> 2, c  = lane & 3;

    float acc[4][4][4];
    #pragma unroll
    for (int mi = 0; mi < 4; mi++)
        #pragma unroll
        for (int ni = 0; ni < 4; ni++)
            #pragma unroll
            for (int q = 0; q < 4; q++) acc[mi][ni][q] = 0.f;

    const int nk = K / 16;
    float4 ra[2], rb[2];

    load_tile<A_KC>(A, lda, bi, 0, ra);
    load_tile<B_KC>(B, ldb, bj, 0, rb);
    store_tile<A_KC>(As[0], ra);
    store_tile<B_KC>(Bs[0], rb);
    __syncthreads();

    for (int ch = 0; ch < nk; ch++) {
        const int buf = ch & 1;
        if (ch + 1 < nk) {
            load_tile<A_KC>(A, lda, bi, (ch + 1) * 16, ra);
            load_tile<B_KC>(B, ldb, bj, (ch + 1) * 16, rb);
        }
        #pragma unroll
        for (int s = 0; s < 2; s++) {
            const float* A_ = &As[buf][(s * 8) * ROWP];
            const float* B_ = &Bs[buf][(s * 8) * ROWP];
            uint32_t af[4][4], bf[4][2];
            #pragma unroll
            for (int mi = 0; mi < 4; mi++) {
                int m = wm * 64 + mi * 16 + r;
                af[mi][0] = __float_as_uint(A_[(c    ) * ROWP + m]);
                af[mi][1] = __float_as_uint(A_[(c    ) * ROWP + m + 8]);
                af[mi][2] = __float_as_uint(A_[(c + 4) * ROWP + m]);
                af[mi][3] = __float_as_uint(A_[(c + 4) * ROWP + m + 8]);
            }
            #pragma unroll
            for (int ni = 0; ni < 4; ni++) {
                int n = wn * 32 + ni * 8 + r;
                bf[ni][0] = __float_as_uint(B_[(c    ) * ROWP + n]);
                bf[ni][1] = __float_as_uint(B_[(c + 4) * ROWP + n]);
            }
            #pragma unroll
            for (int mi = 0; mi < 4; mi++)
                #pragma unroll
                for (int ni = 0; ni < 4; ni++)
                    mma_tf32(acc[mi][ni], af[mi], bf[ni]);
        }
        if (ch + 1 < nk) {
            __syncthreads();
            store_tile<A_KC>(As[1 - buf], ra);
            store_tile<B_KC>(Bs[1 - buf], rb);
            __syncthreads();
        }
    }

    // epilogue
    #pragma unroll
    for (int mi = 0; mi < 4; mi++) {
        int row = bi + wm * 64 + mi * 16 + r;
        float bv0 = bias ? bias[row]     : 0.f;
        float bv1 = bias ? bias[row + 8] : 0.f;
        #pragma unroll
        for (int ni = 0; ni < 4; ni++) {
            int col = bj + wn * 32 + ni * 8 + 2 * c;
            float2 o0, o1;
            o0.x = acc[mi][ni][0] * alpha + bv0;
            o0.y = acc[mi][ni][1] * alpha + bv0;
            o1.x = acc[mi][ni][2] * alpha + bv1;
            o1.y = acc[mi][ni][3] * alpha + bv1;
            if (resid) {
                const float* R = resid + (long long)blockIdx.z * sR;
                float2 r0 = *(const float2*)(R + (long long)row * N + col);
                float2 r1 = *(const float2*)(R + (long long)(row + 8) * N + col);
                o0.x += r0.x; o0.y += r0.y;
                o1.x += r1.x; o1.y += r1.y;
            }
            *(float2*)(C + (long long)row * N + col)       = o0;
            *(float2*)(C + (long long)(row + 8) * N + col) = o1;
        }
    }
}

// ---------------- row softmax (4096 per row) -------------------------------
__global__ void softmax_rows(float* __restrict__ S) {
    float* p = S + (long long)blockIdx.x * NPIX;
    const int t = threadIdx.x;
    float4 v[4];
    float mx = -1e30f;
    #pragma unroll
    for (int j = 0; j < 4; j++) {
        v[j] = ((const float4*)p)[t + j * 256];
        mx = fmaxf(mx, fmaxf(fmaxf(v[j].x, v[j].y), fmaxf(v[j].z, v[j].w)));
    }
    __shared__ float shm[8], shs[8];
    #pragma unroll
    for (int o = 16; o; o >>= 1) mx = fmaxf(mx, __shfl_xor_sync(0xffffffffu, mx, o));
    if ((t & 31) == 0) shm[t >> 5] = mx;
    __syncthreads();
    mx = shm[0];
    #pragma unroll
    for (int i = 1; i < 8; i++) mx = fmaxf(mx, shm[i]);

    float s = 0.f;
    #pragma unroll
    for (int j = 0; j < 4; j++) {
        v[j].x = __expf(v[j].x - mx); v[j].y = __expf(v[j].y - mx);
        v[j].z = __expf(v[j].z - mx); v[j].w = __expf(v[j].w - mx);
        s += v[j].x + v[j].y + v[j].z + v[j].w;
    }
    #pragma unroll
    for (int o = 16; o; o >>= 1) s += __shfl_xor_sync(0xffffffffu, s, o);
    if ((t & 31) == 0) shs[t >> 5] = s;
    __syncthreads();
    s = 0.f;
    #pragma unroll
    for (int i = 0; i < 8; i++) s += shs[i];
    float inv = 1.f / s;
    #pragma unroll
    for (int j = 0; j < 4; j++) {
        v[j].x *= inv; v[j].y *= inv; v[j].z *= inv; v[j].w *= inv;
        ((float4*)p)[t + j * 256] = v[j];
    }
}

// ---------------- launch ---------------------------------------------------
extern "C" void kernel_launch(void* const* d_in, const int* in_sizes, int n_in,
                              void* d_out, int out_size) {
    const float* x     = (const float*)d_in[0];
    const float* gamma = (const float*)d_in[1];
    const float* beta  = (const float*)d_in[2];
    const float* wq    = (const float*)d_in[3];
    const float* bq    = (const float*)d_in[4];
    const float* wk    = (const float*)d_in[5];
    const float* bk    = (const float*)d_in[6];
    const float* wv    = (const float*)d_in[7];
    const float* bv    = (const float*)d_in[8];
    const float* wo    = (const float*)d_in[9];
    const float* bo    = (const float*)d_in[10];
    float* out = (float*)d_out;

    float *hn, *q, *k, *v, *o, *S;
    cudaGetSymbolAddress((void**)&hn, g_hn);
    cudaGetSymbolAddress((void**)&q,  g_q);
    cudaGetSymbolAddress((void**)&k,  g_k);
    cudaGetSymbolAddress((void**)&v,  g_v);
    cudaGetSymbolAddress((void**)&o,  g_o);
    cudaGetSymbolAddress((void**)&S,  g_S);

    const long long P  = (long long)CH * NPIX;     // 2097152
    const long long PS = (long long)NPIX * NPIX;   // 16777216
    const float scale  = 0.044194173824159216f;    // 512^-0.5

    gn_stats<<<BATCH * GROUPS, 256>>>(x);
    gn_apply<<<(int)((long long)BATCH * CH * NPIX / 4 / 256), 256>>>(x, gamma, beta);

    dim3 gProj(NPIX / 128, CH / 128, BATCH);   // (32, 4, 4)
    // projections: A = W (K-contig, lda=CH), B = hn (K-major, ldb=NPIX)
    gemm_tc<true,  false><<<gProj, 256>>>(wq, hn, q, CH, NPIX, CH, CH, NPIX, 0, P, P, 1.f, bq, nullptr, 0);
    gemm_tc<true,  false><<<gProj, 256>>>(wk, hn, k, CH, NPIX, CH, CH, NPIX, 0, P, P, 1.f, bk, nullptr, 0);
    gemm_tc<true,  false><<<gProj, 256>>>(wv, hn, v, CH, NPIX, CH, CH, NPIX, 0, P, P, 1.f, bv, nullptr, 0);

    // S = (Q^T K) * scale : A = q (K-major, lda=NPIX), B = k (K-major, ldb=NPIX)
    dim3 gS(NPIX / 128, NPIX / 128, BATCH);    // (32, 32, 4)
    gemm_tc<false, false><<<gS, 256>>>(q, k, S, NPIX, NPIX, CH, NPIX, NPIX, P, P, PS, scale, nullptr, nullptr, 0);

    softmax_rows<<<BATCH * NPIX, 256>>>(S);

    // O = V P^T : A = v (K-contig over pixels, lda=NPIX), B = S rows (K-contig, ldb=NPIX)
    gemm_tc<true,  true ><<<gProj, 256>>>(v, S, o, CH, NPIX, NPIX, NPIX, NPIX, P, PS, P, 1.f, nullptr, nullptr, 0);

    // out = Wo * O + bo + x
    gemm_tc<true,  false><<<gProj, 256>>>(wo, o, out, CH, NPIX, CH, CH, NPIX, 0, P, P, 1.f, bo, x, P);
}